// round 15
// baseline (speedup 1.0000x reference)
#include <cuda_runtime.h>
#include <cstddef>

#define BB   2
#define LL   512
#define HH   128
#define NH   8
#define HD   16

// ---------------- scratch (static device globals; no allocs) ----------------
__device__ float g_q  [BB*LL*HH];            // Q projection        [b,l,128]
__device__ float g_ka [BB*LL*HH];            // K + abs_pos_k       [b,l,128]
__device__ float g_va [BB*LL*HH];            // V + abs_pos_v       [b,l,128]

// ---------------- kernel 1: QKV projections as tiled GEMM -------------------
__global__ void __launch_bounds__(256) k_proj(
    const float* __restrict__ x,  const float* __restrict__ apk,
    const float* __restrict__ apv,
    const float* __restrict__ Wq, const float* __restrict__ bq,
    const float* __restrict__ Wk, const float* __restrict__ bk,
    const float* __restrict__ Wv, const float* __restrict__ bv)
{
    __shared__ float Xs[32][68];   // [kc][token]
    __shared__ float Ws[32][36];   // [kc][out]

    int t  = threadIdx.x;
    int m0 = blockIdx.x * 64;      // token tile base
    int n0 = blockIdx.y * 32;      // output tile base
    int z  = blockIdx.z;           // matrix select

    const float* W;  const float* bias; const float* add; float* dst;
    if (z == 0)      { W = Wq; bias = bq; add = nullptr; dst = g_q;  }
    else if (z == 1) { W = Wk; bias = bk; add = apk;     dst = g_ka; }
    else             { W = Wv; bias = bv; add = apv;     dst = g_va; }

    int tm = t >> 3;               // 0..31 -> 2 tokens each
    int tn = t & 7;                // 0..7  -> 4 outputs each

    float4 acc0 = make_float4(0.f,0.f,0.f,0.f);
    float4 acc1 = make_float4(0.f,0.f,0.f,0.f);

    for (int k0 = 0; k0 < HH; k0 += 32) {
        {
            int idx = t;
#pragma unroll
            for (int rep = 0; rep < 2; rep++, idx += 256) {
                int m = idx >> 3, k4 = idx & 7;
                float4 v = *reinterpret_cast<const float4*>(
                    &x[(size_t)(m0 + m)*HH + k0 + k4*4]);
                Xs[k4*4+0][m] = v.x; Xs[k4*4+1][m] = v.y;
                Xs[k4*4+2][m] = v.z; Xs[k4*4+3][m] = v.w;
            }
        }
        {
            int kc = t >> 3, n4 = t & 7;
            float4 v = *reinterpret_cast<const float4*>(
                &W[(size_t)(k0 + kc)*HH + n0 + n4*4]);
            *reinterpret_cast<float4*>(&Ws[kc][n4*4]) = v;
        }
        __syncthreads();
#pragma unroll
        for (int kc = 0; kc < 32; kc++) {
            float4 w = *reinterpret_cast<const float4*>(&Ws[kc][tn*4]);
            float x0 = Xs[kc][tm*2 + 0];
            float x1 = Xs[kc][tm*2 + 1];
            acc0.x = fmaf(x0, w.x, acc0.x); acc0.y = fmaf(x0, w.y, acc0.y);
            acc0.z = fmaf(x0, w.z, acc0.z); acc0.w = fmaf(x0, w.w, acc0.w);
            acc1.x = fmaf(x1, w.x, acc1.x); acc1.y = fmaf(x1, w.y, acc1.y);
            acc1.z = fmaf(x1, w.z, acc1.z); acc1.w = fmaf(x1, w.w, acc1.w);
        }
        __syncthreads();
    }

    float4 bz = *reinterpret_cast<const float4*>(&bias[n0 + tn*4]);
    acc0.x += bz.x; acc0.y += bz.y; acc0.z += bz.z; acc0.w += bz.w;
    acc1.x += bz.x; acc1.y += bz.y; acc1.z += bz.z; acc1.w += bz.w;

    size_t o0 = (size_t)(m0 + tm*2 + 0)*HH + n0 + tn*4;
    size_t o1 = (size_t)(m0 + tm*2 + 1)*HH + n0 + tn*4;
    if (add) {
        float4 a0 = *reinterpret_cast<const float4*>(&add[o0]);
        float4 a1 = *reinterpret_cast<const float4*>(&add[o1]);
        acc0.x += a0.x; acc0.y += a0.y; acc0.z += a0.z; acc0.w += a0.w;
        acc1.x += a1.x; acc1.y += a1.y; acc1.z += a1.z; acc1.w += a1.w;
    }
    *reinterpret_cast<float4*>(&dst[o0]) = acc0;
    *reinterpret_cast<float4*>(&dst[o1]) = acc1;
}

// ---------------- kernel 2: single-pass online-softmax attention ------------
// R12's proven online-softmax loop, now at 7 CTAs/SM: 148*7 = 1036 slots >=
// 1024 blocks -> SINGLE WAVE, no 13.5% two-wave tail. Unroll-1 keeps regs
// under the 36-reg cap; 56 warps/SM x 4 LDG.128 in flight >> BDP.
__global__ void __launch_bounds__(256, 7) k_fused(
    const float* __restrict__ time_k,
    const float* __restrict__ time_v,
    const float* __restrict__ mask,
    const float* __restrict__ Wo,
    const float* __restrict__ bo,
    float* __restrict__ out)
{
    int bq = blockIdx.x;                 // b*L + q
    int b  = bq >> 9, q = bq & 511;
    __shared__ __align__(16) float qs[HH];      // q, later ctx
    __shared__ float ms[LL];                    // mask, later out-proj partials
    __shared__ float4 accbuf[8*32];             // per-warp partial ctx
    __shared__ float mbuf[8*NH], sbuf[8*NH];    // per-warp per-head (m, s)

    int t = threadIdx.x, w = t >> 5, l = t & 31;

    if (t < HH) qs[t] = g_q[(size_t)bq*HH + t];
    {
        const float* mrow = mask + ((size_t)b*LL + q)*LL;
        for (int k = t; k < LL; k += 256) ms[k] = mrow[k];
    }
    __syncthreads();

    int h  = l >> 2;
    int k0 = w * 64;
    float4 qv = reinterpret_cast<const float4*>(qs)[l];

    const float4* kab = reinterpret_cast<const float4*>(g_ka + (size_t)b*(LL*HH)) + l;
    const float4* vab = reinterpret_cast<const float4*>(g_va + (size_t)b*(LL*HH)) + l;
    const float4* tkb = reinterpret_cast<const float4*>(time_k + (size_t)bq*(LL*HH)) + l;
    const float4* tvb = reinterpret_cast<const float4*>(time_v + (size_t)bq*(LL*HH)) + l;

    float  m_run = -1e30f, s_run = 0.f;
    float4 acc = make_float4(0.f, 0.f, 0.f, 0.f);

    for (int k = k0; k < k0 + 64; k++) {
        float4 a = tkb[(size_t)k*32];
        float4 c = kab[(size_t)k*32];
        float4 v = tvb[(size_t)k*32];
        float4 d = vab[(size_t)k*32];

        float p = (a.x+c.x)*qv.x + (a.y+c.y)*qv.y
                + (a.z+c.z)*qv.z + (a.w+c.w)*qv.w;
        p += __shfl_xor_sync(0xffffffffu, p, 1);
        p += __shfl_xor_sync(0xffffffffu, p, 2);

        float s0 = fmaf(p, 0.25f, ms[k]);
        float mn = fmaxf(m_run, s0);
        float sc = __expf(m_run - mn);
        float e0 = __expf(s0 - mn);
        s_run = fmaf(s_run, sc, e0);
        acc.x = fmaf(acc.x, sc, e0*(v.x+d.x));
        acc.y = fmaf(acc.y, sc, e0*(v.y+d.y));
        acc.z = fmaf(acc.z, sc, e0*(v.z+d.z));
        acc.w = fmaf(acc.w, sc, e0*(v.w+d.w));
        m_run = mn;
    }

    accbuf[w*32 + l] = acc;
    if ((l & 3) == 0) {                 // m/s identical across the quad
        mbuf[w*NH + h] = m_run;
        sbuf[w*NH + h] = s_run;
    }
    __syncthreads();

    // ---- cross-warp softmax merge (32 lanes, one per float4 of ctx) ----
    if (t < 32) {
        int hh = t >> 2;
        float M = -1e30f;
#pragma unroll
        for (int ww = 0; ww < 8; ww++) M = fmaxf(M, mbuf[ww*NH + hh]);
        float4 tot = make_float4(0.f, 0.f, 0.f, 0.f);
        float  st  = 0.f;
#pragma unroll
        for (int ww = 0; ww < 8; ww++) {
            float f = __expf(mbuf[ww*NH + hh] - M);
            float4 u = accbuf[ww*32 + t];
            tot.x = fmaf(f, u.x, tot.x);
            tot.y = fmaf(f, u.y, tot.y);
            tot.z = fmaf(f, u.z, tot.z);
            tot.w = fmaf(f, u.w, tot.w);
            st = fmaf(f, sbuf[ww*NH + hh], st);
        }
        float inv = 1.f / st;
        tot.x *= inv; tot.y *= inv; tot.z *= inv; tot.w *= inv;
        reinterpret_cast<float4*>(qs)[t] = tot;   // ctx row into smem
    }
    __syncthreads();

    // ---- epilogue: out[bq] = ctx @ Wo + bo (split-K over 2 thread halves) ---
    {
        int j = t & 127, half = t >> 7;
        const float* Wrow = Wo + (size_t)(half*64)*HH + j;
        float a = 0.f;
#pragma unroll 8
        for (int i = 0; i < 64; i++)
            a = fmaf(qs[half*64 + i], Wrow[(size_t)i*HH], a);
        ms[half*128 + j] = a;                   // reuse mask smem as reducer
    }
    __syncthreads();
    if (t < HH)
        out[(size_t)bq*HH + t] = ms[t] + ms[128 + t] + bo[t];
}

// ---------------- launch ----------------------------------------------------
extern "C" void kernel_launch(void* const* d_in, const int* in_sizes, int n_in,
                              void* d_out, int out_size)
{
    const float* x      = (const float*)d_in[0];
    const float* time_k = (const float*)d_in[1];
    const float* time_v = (const float*)d_in[2];
    const float* apk    = (const float*)d_in[3];
    const float* apv    = (const float*)d_in[4];
    const float* mask   = (const float*)d_in[5];
    const float* Wq     = (const float*)d_in[6];
    const float* bq     = (const float*)d_in[7];
    const float* Wk     = (const float*)d_in[8];
    const float* bk     = (const float*)d_in[9];
    const float* Wv     = (const float*)d_in[10];
    const float* bv     = (const float*)d_in[11];
    const float* Wo     = (const float*)d_in[12];
    const float* bo     = (const float*)d_in[13];

    {
        dim3 g(16, 4, 3);     // 16 token tiles x 4 output tiles x 3 matrices
        k_proj<<<g, 256>>>(x, apk, apv, Wq, bq, Wk, bk, Wv, bv);
    }
    k_fused<<<BB*LL, 256>>>(time_k, time_v, mask, Wo, bo, (float*)d_out);
}

// round 16
// speedup vs baseline: 1.2638x; 1.2638x over previous
#include <cuda_runtime.h>
#include <cstddef>

#define BB   2
#define LL   512
#define HH   128
#define NH   8
#define HD   16

// ---------------- scratch (static device globals; no allocs) ----------------
__device__ float g_q  [BB*LL*HH];            // Q projection        [b,l,128]
__device__ float g_ka [BB*LL*HH];            // K + abs_pos_k       [b,l,128]
__device__ float g_va [BB*LL*HH];            // V + abs_pos_v       [b,l,128]

// ---------------- kernel 1: QKV projections as tiled GEMM -------------------
__global__ void __launch_bounds__(256) k_proj(
    const float* __restrict__ x,  const float* __restrict__ apk,
    const float* __restrict__ apv,
    const float* __restrict__ Wq, const float* __restrict__ bq,
    const float* __restrict__ Wk, const float* __restrict__ bk,
    const float* __restrict__ Wv, const float* __restrict__ bv)
{
    __shared__ float Xs[32][68];   // [kc][token]
    __shared__ float Ws[32][36];   // [kc][out]

    int t  = threadIdx.x;
    int m0 = blockIdx.x * 64;      // token tile base
    int n0 = blockIdx.y * 32;      // output tile base
    int z  = blockIdx.z;           // matrix select

    const float* W;  const float* bias; const float* add; float* dst;
    if (z == 0)      { W = Wq; bias = bq; add = nullptr; dst = g_q;  }
    else if (z == 1) { W = Wk; bias = bk; add = apk;     dst = g_ka; }
    else             { W = Wv; bias = bv; add = apv;     dst = g_va; }

    int tm = t >> 3;               // 0..31 -> 2 tokens each
    int tn = t & 7;                // 0..7  -> 4 outputs each

    float4 acc0 = make_float4(0.f,0.f,0.f,0.f);
    float4 acc1 = make_float4(0.f,0.f,0.f,0.f);

    for (int k0 = 0; k0 < HH; k0 += 32) {
        {
            int idx = t;
#pragma unroll
            for (int rep = 0; rep < 2; rep++, idx += 256) {
                int m = idx >> 3, k4 = idx & 7;
                float4 v = *reinterpret_cast<const float4*>(
                    &x[(size_t)(m0 + m)*HH + k0 + k4*4]);
                Xs[k4*4+0][m] = v.x; Xs[k4*4+1][m] = v.y;
                Xs[k4*4+2][m] = v.z; Xs[k4*4+3][m] = v.w;
            }
        }
        {
            int kc = t >> 3, n4 = t & 7;
            float4 v = *reinterpret_cast<const float4*>(
                &W[(size_t)(k0 + kc)*HH + n0 + n4*4]);
            *reinterpret_cast<float4*>(&Ws[kc][n4*4]) = v;
        }
        __syncthreads();
#pragma unroll
        for (int kc = 0; kc < 32; kc++) {
            float4 w = *reinterpret_cast<const float4*>(&Ws[kc][tn*4]);
            float x0 = Xs[kc][tm*2 + 0];
            float x1 = Xs[kc][tm*2 + 1];
            acc0.x = fmaf(x0, w.x, acc0.x); acc0.y = fmaf(x0, w.y, acc0.y);
            acc0.z = fmaf(x0, w.z, acc0.z); acc0.w = fmaf(x0, w.w, acc0.w);
            acc1.x = fmaf(x1, w.x, acc1.x); acc1.y = fmaf(x1, w.y, acc1.y);
            acc1.z = fmaf(x1, w.z, acc1.z); acc1.w = fmaf(x1, w.w, acc1.w);
        }
        __syncthreads();
    }

    float4 bz = *reinterpret_cast<const float4*>(&bias[n0 + tn*4]);
    acc0.x += bz.x; acc0.y += bz.y; acc0.z += bz.z; acc0.w += bz.w;
    acc1.x += bz.x; acc1.y += bz.y; acc1.z += bz.z; acc1.w += bz.w;

    size_t o0 = (size_t)(m0 + tm*2 + 0)*HH + n0 + tn*4;
    size_t o1 = (size_t)(m0 + tm*2 + 1)*HH + n0 + tn*4;
    if (add) {
        float4 a0 = *reinterpret_cast<const float4*>(&add[o0]);
        float4 a1 = *reinterpret_cast<const float4*>(&add[o1]);
        acc0.x += a0.x; acc0.y += a0.y; acc0.z += a0.z; acc0.w += a0.w;
        acc1.x += a1.x; acc1.y += a1.y; acc1.z += a1.z; acc1.w += a1.w;
    }
    *reinterpret_cast<float4*>(&dst[o0]) = acc0;
    *reinterpret_cast<float4*>(&dst[o1]) = acc1;
}

// ---------------- kernel 2: online-softmax, 2 queries/block, (256,4) --------
// R12's optimal operating point (unroll-2-equivalent ILP, 4 CTAs/SM, 32
// warps/SM) with its two known losses removed:
//  - grid 512 <= 592 resident slots -> SINGLE wave (R12 paid ~13% 2-wave tail)
//  - ka/va and Wo read once per 2 queries -> L2 traffic -256MB
// Register budget ~60 <= 64-reg cap (R13 failed this at 80 regs / 3 CTAs).
__global__ void __launch_bounds__(256, 4) k_fused(
    const float* __restrict__ time_k,
    const float* __restrict__ time_v,
    const float* __restrict__ mask,
    const float* __restrict__ Wo,
    const float* __restrict__ bo,
    float* __restrict__ out)
{
    int bq0 = blockIdx.x * 2;            // first of 2 consecutive queries
    int b   = bq0 >> 9, q0 = bq0 & 511;  // q1 = q0+1 (same batch; L even)
    __shared__ __align__(16) float qs2[2][HH];   // q rows, later ctx rows
    __shared__ float ms2[2][LL];                 // mask rows, later reducers
    __shared__ float4 accbuf[2][8*32];           // per-query per-warp ctx
    __shared__ float mbuf[2][8*NH], sbuf[2][8*NH];

    int t = threadIdx.x, w = t >> 5, l = t & 31;

    if (t < 2*HH) qs2[t >> 7][t & 127] = g_q[(size_t)(bq0 + (t >> 7))*HH + (t & 127)];
    for (int i = t; i < 2*LL; i += 256)
        ms2[i >> 9][i & 511] = mask[((size_t)b*LL + q0 + (i >> 9))*LL + (i & 511)];
    __syncthreads();

    int h  = l >> 2;
    int k0 = w * 64;
    float4 qv0 = reinterpret_cast<const float4*>(qs2[0])[l];
    float4 qv1 = reinterpret_cast<const float4*>(qs2[1])[l];

    const float4* kab  = reinterpret_cast<const float4*>(g_ka + (size_t)b*(LL*HH)) + l;
    const float4* vab  = reinterpret_cast<const float4*>(g_va + (size_t)b*(LL*HH)) + l;
    const float4* tk0b = reinterpret_cast<const float4*>(time_k + (size_t)(bq0  )*(LL*HH)) + l;
    const float4* tk1b = reinterpret_cast<const float4*>(time_k + (size_t)(bq0+1)*(LL*HH)) + l;
    const float4* tv0b = reinterpret_cast<const float4*>(time_v + (size_t)(bq0  )*(LL*HH)) + l;
    const float4* tv1b = reinterpret_cast<const float4*>(time_v + (size_t)(bq0+1)*(LL*HH)) + l;

    float  m0r = -1e30f, s0r = 0.f, m1r = -1e30f, s1r = 0.f;
    float4 acc0 = make_float4(0.f,0.f,0.f,0.f);
    float4 acc1 = make_float4(0.f,0.f,0.f,0.f);

    for (int k = k0; k < k0 + 64; k++) {
        // 6 outstanding LDG.128 per lane; c/d serve both queries
        float4 c  = kab [(size_t)k*32];
        float4 d  = vab [(size_t)k*32];
        float4 a0 = tk0b[(size_t)k*32];
        float4 a1 = tk1b[(size_t)k*32];
        float4 v0 = tv0b[(size_t)k*32];
        float4 v1 = tv1b[(size_t)k*32];

        float p0 = (a0.x+c.x)*qv0.x + (a0.y+c.y)*qv0.y
                 + (a0.z+c.z)*qv0.z + (a0.w+c.w)*qv0.w;
        float p1 = (a1.x+c.x)*qv1.x + (a1.y+c.y)*qv1.y
                 + (a1.z+c.z)*qv1.z + (a1.w+c.w)*qv1.w;
        p0 += __shfl_xor_sync(0xffffffffu, p0, 1);
        p0 += __shfl_xor_sync(0xffffffffu, p0, 2);
        p1 += __shfl_xor_sync(0xffffffffu, p1, 1);
        p1 += __shfl_xor_sync(0xffffffffu, p1, 2);

        // shared value-row adds
        float vx0 = v0.x+d.x, vy0 = v0.y+d.y, vz0 = v0.z+d.z, vw0 = v0.w+d.w;
        float vx1 = v1.x+d.x, vy1 = v1.y+d.y, vz1 = v1.z+d.z, vw1 = v1.w+d.w;

        {   // query 0 online update
            float s0 = fmaf(p0, 0.25f, ms2[0][k]);
            float mn = fmaxf(m0r, s0);
            float sc = __expf(m0r - mn);
            float e0 = __expf(s0 - mn);
            s0r = fmaf(s0r, sc, e0);
            acc0.x = fmaf(acc0.x, sc, e0*vx0);
            acc0.y = fmaf(acc0.y, sc, e0*vy0);
            acc0.z = fmaf(acc0.z, sc, e0*vz0);
            acc0.w = fmaf(acc0.w, sc, e0*vw0);
            m0r = mn;
        }
        {   // query 1 online update (independent chain)
            float s1 = fmaf(p1, 0.25f, ms2[1][k]);
            float mn = fmaxf(m1r, s1);
            float sc = __expf(m1r - mn);
            float e1 = __expf(s1 - mn);
            s1r = fmaf(s1r, sc, e1);
            acc1.x = fmaf(acc1.x, sc, e1*vx1);
            acc1.y = fmaf(acc1.y, sc, e1*vy1);
            acc1.z = fmaf(acc1.z, sc, e1*vz1);
            acc1.w = fmaf(acc1.w, sc, e1*vw1);
            m1r = mn;
        }
    }

    accbuf[0][w*32 + l] = acc0;
    accbuf[1][w*32 + l] = acc1;
    if ((l & 3) == 0) {
        mbuf[0][w*NH + h] = m0r;  sbuf[0][w*NH + h] = s0r;
        mbuf[1][w*NH + h] = m1r;  sbuf[1][w*NH + h] = s1r;
    }
    __syncthreads();

    // ---- cross-warp softmax merge: t<64, qq = t>>5, lane = t&31 ----
    if (t < 64) {
        int qq = t >> 5, ln = t & 31, hh = ln >> 2;
        float M = -1e30f;
#pragma unroll
        for (int ww = 0; ww < 8; ww++) M = fmaxf(M, mbuf[qq][ww*NH + hh]);
        float4 tot = make_float4(0.f, 0.f, 0.f, 0.f);
        float  st  = 0.f;
#pragma unroll
        for (int ww = 0; ww < 8; ww++) {
            float f = __expf(mbuf[qq][ww*NH + hh] - M);
            float4 u = accbuf[qq][ww*32 + ln];
            tot.x = fmaf(f, u.x, tot.x);
            tot.y = fmaf(f, u.y, tot.y);
            tot.z = fmaf(f, u.z, tot.z);
            tot.w = fmaf(f, u.w, tot.w);
            st = fmaf(f, sbuf[qq][ww*NH + hh], st);
        }
        float inv = 1.f / st;
        tot.x *= inv; tot.y *= inv; tot.z *= inv; tot.w *= inv;
        reinterpret_cast<float4*>(qs2[qq])[ln] = tot;   // ctx rows into smem
    }
    __syncthreads();

    // ---- epilogue: both queries' out = ctx @ Wo + bo, Wo read once ----
    {
        int j = t & 127, half = t >> 7;
        const float* Wrow = Wo + (size_t)(half*64)*HH + j;
        float a0 = 0.f, a1 = 0.f;
#pragma unroll 8
        for (int i = 0; i < 64; i++) {
            float wv = Wrow[(size_t)i*HH];
            a0 = fmaf(qs2[0][half*64 + i], wv, a0);
            a1 = fmaf(qs2[1][half*64 + i], wv, a1);
        }
        ms2[0][half*128 + j] = a0;
        ms2[1][half*128 + j] = a1;
    }
    __syncthreads();
    if (t < HH) {
        out[(size_t)(bq0  )*HH + t] = ms2[0][t] + ms2[0][128 + t] + bo[t];
        out[(size_t)(bq0+1)*HH + t] = ms2[1][t] + ms2[1][128 + t] + bo[t];
    }
}

// ---------------- launch ----------------------------------------------------
extern "C" void kernel_launch(void* const* d_in, const int* in_sizes, int n_in,
                              void* d_out, int out_size)
{
    const float* x      = (const float*)d_in[0];
    const float* time_k = (const float*)d_in[1];
    const float* time_v = (const float*)d_in[2];
    const float* apk    = (const float*)d_in[3];
    const float* apv    = (const float*)d_in[4];
    const float* mask   = (const float*)d_in[5];
    const float* Wq     = (const float*)d_in[6];
    const float* bq     = (const float*)d_in[7];
    const float* Wk     = (const float*)d_in[8];
    const float* bk     = (const float*)d_in[9];
    const float* Wv     = (const float*)d_in[10];
    const float* bv     = (const float*)d_in[11];
    const float* Wo     = (const float*)d_in[12];
    const float* bo     = (const float*)d_in[13];

    {
        dim3 g(16, 4, 3);     // 16 token tiles x 4 output tiles x 3 matrices
        k_proj<<<g, 256>>>(x, apk, apv, Wq, bq, Wk, bk, Wv, bv);
    }
    k_fused<<<BB*LL/2, 256>>>(time_k, time_v, mask, Wo, bo, (float*)d_out);
}

// round 17
// speedup vs baseline: 1.3781x; 1.0905x over previous
#include <cuda_runtime.h>
#include <cstddef>

#define BB   2
#define LL   512
#define HH   128
#define NH   8
#define HD   16

// ---------------- scratch (static device globals; no allocs) ----------------
__device__ float g_q  [BB*LL*HH];            // Q projection        [b,l,128]
__device__ float g_ka [BB*LL*HH];            // K + abs_pos_k       [b,l,128]
__device__ float g_va [BB*LL*HH];            // V + abs_pos_v       [b,l,128]

// ---------------- kernel 1: QKV projections, 64x16 tiles, 384 blocks --------
// Latency-bound kernel -> more blocks (2.6/SM) + half the per-thread chain.
__global__ void __launch_bounds__(256) k_proj(
    const float* __restrict__ x,  const float* __restrict__ apk,
    const float* __restrict__ apv,
    const float* __restrict__ Wq, const float* __restrict__ bq,
    const float* __restrict__ Wk, const float* __restrict__ bk,
    const float* __restrict__ Wv, const float* __restrict__ bv)
{
    __shared__ float Xs[32][68];   // [kc][token]
    __shared__ float Ws[32][20];   // [kc][out16]

    int t  = threadIdx.x;
    int m0 = blockIdx.x * 64;      // token tile base (16 tiles)
    int n0 = blockIdx.y * 16;      // output tile base (8 tiles)
    int z  = blockIdx.z;           // matrix select

    const float* W;  const float* bias; const float* add; float* dst;
    if (z == 0)      { W = Wq; bias = bq; add = nullptr; dst = g_q;  }
    else if (z == 1) { W = Wk; bias = bk; add = apk;     dst = g_ka; }
    else             { W = Wv; bias = bv; add = apv;     dst = g_va; }

    int tm = t >> 2;               // 0..63 -> 1 token each
    int tn = t & 3;                // 0..3  -> 4 outputs each

    float4 acc = make_float4(0.f,0.f,0.f,0.f);

    for (int k0 = 0; k0 < HH; k0 += 32) {
        // X chunk (64 tokens x 32 k), transposed into Xs[k][m]
        {
            int idx = t;
#pragma unroll
            for (int rep = 0; rep < 2; rep++, idx += 256) {
                int m = idx >> 3, k4 = idx & 7;
                float4 v = *reinterpret_cast<const float4*>(
                    &x[(size_t)(m0 + m)*HH + k0 + k4*4]);
                Xs[k4*4+0][m] = v.x; Xs[k4*4+1][m] = v.y;
                Xs[k4*4+2][m] = v.z; Xs[k4*4+3][m] = v.w;
            }
        }
        // W chunk (32 k x 16 outs)
        if (t < 128) {
            int kc = t >> 2, n4 = t & 3;
            float4 v = *reinterpret_cast<const float4*>(
                &W[(size_t)(k0 + kc)*HH + n0 + n4*4]);
            *reinterpret_cast<float4*>(&Ws[kc][n4*4]) = v;
        }
        __syncthreads();
#pragma unroll
        for (int kc = 0; kc < 32; kc++) {
            float4 w = *reinterpret_cast<const float4*>(&Ws[kc][tn*4]);
            float xv = Xs[kc][tm];
            acc.x = fmaf(xv, w.x, acc.x); acc.y = fmaf(xv, w.y, acc.y);
            acc.z = fmaf(xv, w.z, acc.z); acc.w = fmaf(xv, w.w, acc.w);
        }
        __syncthreads();
    }

    float4 bz = *reinterpret_cast<const float4*>(&bias[n0 + tn*4]);
    acc.x += bz.x; acc.y += bz.y; acc.z += bz.z; acc.w += bz.w;

    size_t o = (size_t)(m0 + tm)*HH + n0 + tn*4;
    if (add) {
        float4 a = *reinterpret_cast<const float4*>(&add[o]);
        acc.x += a.x; acc.y += a.y; acc.z += a.z; acc.w += a.w;
    }
    *reinterpret_cast<float4*>(&dst[o]) = acc;
}

// ---------------- kernel 2: single-pass online-softmax attention ------------
// EXACT R12 champion (96.1us) + __ldcs streaming hints on time_k/time_v
// (touched-once data, evict-first: protects ka/va/Wo L2 residency).
__global__ void __launch_bounds__(256, 4) k_fused(
    const float* __restrict__ time_k,
    const float* __restrict__ time_v,
    const float* __restrict__ mask,
    const float* __restrict__ Wo,
    const float* __restrict__ bo,
    float* __restrict__ out)
{
    int bq = blockIdx.x;                 // b*L + q
    int b  = bq >> 9, q = bq & 511;
    __shared__ __align__(16) float qs[HH];      // q, later ctx
    __shared__ float ms[LL];                    // mask, later out-proj partials
    __shared__ float4 accbuf[8*32];             // per-warp partial ctx
    __shared__ float mbuf[8*NH], sbuf[8*NH];    // per-warp per-head (m, s)

    int t = threadIdx.x, w = t >> 5, l = t & 31;

    if (t < HH) qs[t] = g_q[(size_t)bq*HH + t];
    {
        const float* mrow = mask + ((size_t)b*LL + q)*LL;
        for (int k = t; k < LL; k += 256) ms[k] = mrow[k];
    }
    __syncthreads();

    int h  = l >> 2;
    int k0 = w * 64;
    float4 qv = reinterpret_cast<const float4*>(qs)[l];

    const float4* kab = reinterpret_cast<const float4*>(g_ka + (size_t)b*(LL*HH)) + l;
    const float4* vab = reinterpret_cast<const float4*>(g_va + (size_t)b*(LL*HH)) + l;
    const float4* tkb = reinterpret_cast<const float4*>(time_k + (size_t)bq*(LL*HH)) + l;
    const float4* tvb = reinterpret_cast<const float4*>(time_v + (size_t)bq*(LL*HH)) + l;

    float  m_run = -1e30f, s_run = 0.f;
    float4 acc = make_float4(0.f, 0.f, 0.f, 0.f);

    for (int k = k0; k < k0 + 64; k += 2) {
        // 8 outstanding LDG.128 per lane; tk/tv streamed evict-first
        float4 a0 = __ldcs(tkb + (size_t)(k+0)*32);
        float4 a1 = __ldcs(tkb + (size_t)(k+1)*32);
        float4 c0 = kab[(size_t)(k+0)*32];
        float4 c1 = kab[(size_t)(k+1)*32];
        float4 b0 = __ldcs(tvb + (size_t)(k+0)*32);
        float4 b1 = __ldcs(tvb + (size_t)(k+1)*32);
        float4 d0 = vab[(size_t)(k+0)*32];
        float4 d1 = vab[(size_t)(k+1)*32];

        float p0 = (a0.x+c0.x)*qv.x + (a0.y+c0.y)*qv.y
                 + (a0.z+c0.z)*qv.z + (a0.w+c0.w)*qv.w;
        float p1 = (a1.x+c1.x)*qv.x + (a1.y+c1.y)*qv.y
                 + (a1.z+c1.z)*qv.z + (a1.w+c1.w)*qv.w;
        // quad reduce -> full head dot on all 4 lanes
        p0 += __shfl_xor_sync(0xffffffffu, p0, 1);
        p0 += __shfl_xor_sync(0xffffffffu, p0, 2);
        p1 += __shfl_xor_sync(0xffffffffu, p1, 1);
        p1 += __shfl_xor_sync(0xffffffffu, p1, 2);

        float s0 = fmaf(p0, 0.25f, ms[k  ]);
        float s1 = fmaf(p1, 0.25f, ms[k+1]);

        float mnew  = fmaxf(m_run, fmaxf(s0, s1));
        float scale = __expf(m_run - mnew);
        float e0    = __expf(s0 - mnew);
        float e1    = __expf(s1 - mnew);
        s_run = fmaf(s_run, scale, e0 + e1);

        acc.x = fmaf(acc.x, scale, fmaf(e0, b0.x+d0.x, e1*(b1.x+d1.x)));
        acc.y = fmaf(acc.y, scale, fmaf(e0, b0.y+d0.y, e1*(b1.y+d1.y)));
        acc.z = fmaf(acc.z, scale, fmaf(e0, b0.z+d0.z, e1*(b1.z+d1.z)));
        acc.w = fmaf(acc.w, scale, fmaf(e0, b0.w+d0.w, e1*(b1.w+d1.w)));
        m_run = mnew;
    }

    accbuf[w*32 + l] = acc;
    if ((l & 3) == 0) {                 // m/s identical across the quad
        mbuf[w*NH + h] = m_run;
        sbuf[w*NH + h] = s_run;
    }
    __syncthreads();

    // ---- cross-warp softmax merge (32 lanes, one per float4 of ctx) ----
    if (t < 32) {
        int hh = t >> 2;
        float M = -1e30f;
#pragma unroll
        for (int ww = 0; ww < 8; ww++) M = fmaxf(M, mbuf[ww*NH + hh]);
        float4 tot = make_float4(0.f, 0.f, 0.f, 0.f);
        float  st  = 0.f;
#pragma unroll
        for (int ww = 0; ww < 8; ww++) {
            float f = __expf(mbuf[ww*NH + hh] - M);
            float4 u = accbuf[ww*32 + t];
            tot.x = fmaf(f, u.x, tot.x);
            tot.y = fmaf(f, u.y, tot.y);
            tot.z = fmaf(f, u.z, tot.z);
            tot.w = fmaf(f, u.w, tot.w);
            st = fmaf(f, sbuf[ww*NH + hh], st);
        }
        float inv = 1.f / st;
        tot.x *= inv; tot.y *= inv; tot.z *= inv; tot.w *= inv;
        reinterpret_cast<float4*>(qs)[t] = tot;   // ctx row into smem
    }
    __syncthreads();

    // ---- epilogue: out[bq] = ctx @ Wo + bo (split-K over 2 thread halves) ---
    {
        int j = t & 127, half = t >> 7;
        const float* Wrow = Wo + (size_t)(half*64)*HH + j;
        float a = 0.f;
#pragma unroll 8
        for (int i = 0; i < 64; i++)
            a = fmaf(qs[half*64 + i], Wrow[(size_t)i*HH], a);
        ms[half*128 + j] = a;                   // reuse mask smem as reducer
    }
    __syncthreads();
    if (t < HH)
        out[(size_t)bq*HH + t] = ms[t] + ms[128 + t] + bo[t];
}

// ---------------- launch ----------------------------------------------------
extern "C" void kernel_launch(void* const* d_in, const int* in_sizes, int n_in,
                              void* d_out, int out_size)
{
    const float* x      = (const float*)d_in[0];
    const float* time_k = (const float*)d_in[1];
    const float* time_v = (const float*)d_in[2];
    const float* apk    = (const float*)d_in[3];
    const float* apv    = (const float*)d_in[4];
    const float* mask   = (const float*)d_in[5];
    const float* Wq     = (const float*)d_in[6];
    const float* bq     = (const float*)d_in[7];
    const float* Wk     = (const float*)d_in[8];
    const float* bk     = (const float*)d_in[9];
    const float* Wv     = (const float*)d_in[10];
    const float* bv     = (const float*)d_in[11];
    const float* Wo     = (const float*)d_in[12];
    const float* bo     = (const float*)d_in[13];

    {
        dim3 g(16, 8, 3);     // 16 token tiles x 8 output tiles x 3 matrices
        k_proj<<<g, 256>>>(x, apk, apv, Wq, bq, Wk, bk, Wv, bv);
    }
    k_fused<<<BB*LL, 256>>>(time_k, time_v, mask, Wo, bo, (float*)d_out);
}